// round 11
// baseline (speedup 1.0000x reference)
#include <cuda_runtime.h>
#include <cuda_bf16.h>
#include <cstdint>

#define NB 4
#define NN 256
#define HH 128
typedef unsigned long long ull;

__device__ float g_A[NB*NN*HH];
__device__ float g_Bv[NB*NN*HH];

// smem byte offsets (pair_gemm) — fp8 images, 288B row stride (18 x 16B chunks)
#define OFF_F    0          // F image  [128 j][288 k] e4m3   (36864B)
#define OFF_W    36864      // Wt image [128 h][288 k] e4m3   (36864B)
#define OFF_XJ   73728      // Xj bf16 pairs u32 [128 j][68]  (34816B)
#define OFF_BJ   108544     // Bj bf16 pairs u32 [128 j][66]  (33792B)
#define OFF_HIS  142336     // hi bf16 pairs u32 [64]
#define OFF_AI   142592     // f32[128]
#define OFF_W2   143104     // f32[128]
#define OFF_RED  143616     // f32[128][2]
#define SMEM_TOT 144640

__device__ __forceinline__ uint32_t s32(const void* p){
  uint32_t a; asm("{ .reg .u64 t; cvta.to.shared.u64 t, %1; cvt.u32.u64 %0, t; }":"=r"(a):"l"(p)); return a;
}
// fp8 image offset by (row, 16B-chunk index 0..17), XOR-swizzled
__device__ __forceinline__ uint32_t f8off(uint32_t r, uint32_t ch){
  return ((r*288u + ch*16u) ^ ((r&7u)<<4));
}
__device__ __forceinline__ uint32_t f2bf(float a,float b){
  __nv_bfloat162 t=__floats2bfloat162_rn(a,b); return *(uint32_t*)&t;
}
// two f32 -> packed e4m3x2 (lo byte = lo)
__device__ __forceinline__ uint16_t cvt8(float hi,float lo){
  uint16_t r; asm("cvt.rn.satfinite.e4m3x2.f32 %0,%1,%2;":"=h"(r):"f"(hi),"f"(lo)); return r;
}
__device__ __forceinline__ uint32_t pk16(uint16_t l,uint16_t h){
  uint32_t r; asm("mov.b32 %0,{%1,%2};":"=r"(r):"h"(l),"h"(h)); return r;
}
__device__ __forceinline__ void cpa16(void* dst,const void* src){
  unsigned d=(unsigned)__cvta_generic_to_shared(dst);
  asm volatile("cp.async.cg.shared.global [%0],[%1],16;\n"::"r"(d),"l"(src));
}
__device__ __forceinline__ void cpcommit(){ asm volatile("cp.async.commit_group;\n"); }

#define LDSM4(r0,r1,r2,r3,a) asm volatile( \
  "ldmatrix.sync.aligned.m8n8.x4.shared.b16 {%0,%1,%2,%3},[%4];" \
  :"=r"(r0),"=r"(r1),"=r"(r2),"=r"(r3):"r"(a))
#define MMAFP8(c,a,b) asm volatile( \
  "mma.sync.aligned.m16n8k32.row.col.f32.e4m3.e4m3.f32 " \
  "{%0,%1,%2,%3},{%4,%5,%6,%7},{%8,%9},{%0,%1,%2,%3};" \
  :"+f"((c)[0]),"+f"((c)[1]),"+f"((c)[2]),"+f"((c)[3]) \
  :"r"((a)[0]),"r"((a)[1]),"r"((a)[2]),"r"((a)[3]),"r"((b)[0]),"r"((b)[1]))

extern __shared__ __align__(1024) char dynsm[];

// ---- Kernel 1: per-node halves (validated R10 version) ----
#define PRE_SMEM (4*HH*4 + 2*2*32*HH*4)
__global__ void __launch_bounds__(256)
precompute_ab(const float* __restrict__ X,
              const float* __restrict__ W1,
              const float* __restrict__ b1){
  float* Xs=(float*)dynsm;
  float* Ws=(float*)(dynsm+4*HH*4);
  int r0=blockIdx.x*4;
  int tid=threadIdx.x;
  int h=tid&127, s=tid>>7;

  for(int e=tid;e<4*HH/4;e+=256)
    ((float4*)Xs)[e]=((const float4*)(X+(size_t)r0*HH))[e];

  #define STAGE(c,buf) do{ \
    for(int e=tid;e<2*32*HH/4;e+=256){ \
      int sh=e>=(32*HH/4); int le=e-sh*(32*HH/4); \
      cpa16((float4*)(Ws+(buf)*2*32*HH+sh*32*HH)+le, \
            (const float4*)(W1+((size_t)(sh*HH+(c)*32))*HH)+le); \
    } cpcommit(); }while(0)

  STAGE(0,0);
  float acc[4]={0.f,0.f,0.f,0.f};
  for(int c=0;c<4;c++){
    if(c<3){ STAGE(c+1,(c+1)&1); asm volatile("cp.async.wait_group 1;\n"); }
    else   { asm volatile("cp.async.wait_group 0;\n"); }
    __syncthreads();
    const float* wp=Ws+(c&1)*2*32*HH+s*32*HH;
#pragma unroll 8
    for(int kk=0;kk<32;kk++){
      float wv=wp[kk*HH+h];
      int k=c*32+kk;
#pragma unroll
      for(int r=0;r<4;r++) acc[r]+=Xs[r*HH+k]*wv;
    }
    __syncthreads();
  }
  if(s==0){
    float bb=b1[h];
#pragma unroll
    for(int r=0;r<4;r++) g_A[(size_t)(r0+r)*HH+h]=acc[r]+bb;
  } else {
#pragma unroll
    for(int r=0;r<4;r++) g_Bv[(size_t)(r0+r)*HH+h]=acc[r];
  }
  #undef STAGE
}

// ---- Kernel 2: FP8 MMA pairwise GEMM + fused epilogue ----
__global__ void __launch_bounds__(256,1)
pair_gemm(const float* __restrict__ X,const float* __restrict__ base,
          const float* __restrict__ comp,const float* __restrict__ W1,
          const float* __restrict__ W2,const float* __restrict__ b2,
          float* __restrict__ out){
  char* sm=dynsm;
  uint32_t smb=s32(sm);
  int tid=threadIdx.x, w=tid>>5, lane=tid&31;
  int jt=blockIdx.x, ig=blockIdx.y, b=blockIdx.z;
  int j0=jt*128;
  int jw=(w&3)*32, hw=(w>>2)*64;
  float b2v=b2[0];

  // ---- once: W image (fp8). h=tid&127, halfk handles chunks 0-7 / 8-15 ----
  {
    int h=tid&127, halfk=tid>>7;
    for(int c=halfk*8;c<halfk*8+8;c++){
      int k0=c*16;
      uint32_t v[4];
#pragma unroll
      for(int q=0;q<4;q++){
        int kb=256+k0+4*q;
        v[q]=pk16(cvt8(W1[(kb+1)*HH+h],W1[(kb+0)*HH+h]),
                  cvt8(W1[(kb+3)*HH+h],W1[(kb+2)*HH+h]));
      }
      *(uint4*)(sm+OFF_W+f8off(h,c))=*(uint4*)v;
    }
    if(tid<128){
      uint32_t v0=pk16(cvt8(W1[513*HH+h],W1[512*HH+h]),
                       cvt8(W1[515*HH+h],W1[514*HH+h]));
      uint32_t v[4]={v0,0u,0u,0u};
      *(uint4*)(sm+OFF_W+f8off(h,16))=*(uint4*)v;
      uint32_t z[4]={0u,0u,0u,0u};
      *(uint4*)(sm+OFF_W+f8off(h,17))=*(uint4*)z;
      *(uint4*)(sm+OFF_F+f8off(h,17))=*(uint4*)z;   // F pad chunk, never rewritten
    }
  }
  // ---- once: Xj bf16 pairs [j][kp] stride 68, Bj pairs [j][hp] stride 66 ----
  for(int idx=tid;idx<64*128;idx+=256){
    int kp=idx&63, j=idx>>6;
    float2 xv=*(const float2*)(X+(size_t)(b*NN+j0+j)*HH+2*kp);
    *(uint32_t*)(sm+OFF_XJ+(j*68+kp)*4)=f2bf(xv.x,xv.y);
  }
  for(int idx=tid;idx<64*128;idx+=256){
    int hp=idx&63, j=idx>>6;
    float2 bv=*(const float2*)(g_Bv+(size_t)(b*NN+j0+j)*HH+2*hp);
    *(uint32_t*)(sm+OFF_BJ+(j*66+hp)*4)=f2bf(bv.x,bv.y);
  }
  if(tid<32) ((float4*)(sm+OFF_W2))[tid]=((const float4*)W2)[tid];
  __syncthreads();

  uint32_t xr=(uint32_t)((lane&7)<<4);
  uint32_t offA = OFF_F + (uint32_t)(jw+(lane&15))*288u + (uint32_t)((lane>>4)*16);
  uint32_t offB[4];
#pragma unroll
  for(int q=0;q<4;q++){
    uint32_t rB=(uint32_t)(hw + q*16 + (lane&7) + ((lane>>4)<<3));
    offB[q]= OFF_W + rB*288u + (uint32_t)(((lane>>3)&1)*16);
  }

  float2 w28[8];
#pragma unroll
  for(int nt=0;nt<8;nt++)
    w28[nt]=*(float2*)(sm+OFF_W2+(hw+nt*8+2*(lane&3))*4);

  for(int itn=0;itn<16;itn++){
    int i=ig*16+itn;
    if(tid<64){
      float2 xv=*(const float2*)(X+(size_t)(b*NN+i)*HH+2*tid);
      *(uint32_t*)(sm+OFF_HIS+tid*4)=f2bf(xv.x,xv.y);
    } else if(tid>=64&&tid<96){
      ((float4*)(sm+OFF_AI))[tid-64]=((const float4*)(g_A+(size_t)(b*NN+i)*HH))[tid-64];
    }
    __syncthreads();

    // build F (fp8): sec0 chunks 0-7 = |hi-hj| (k 0..127), sec1 chunks 8-15 = hi*hj
    {
      int j=tid&127, sec=tid>>7;
      const char* xjrow=sm+OFF_XJ+(size_t)j*272;
#pragma unroll 2
      for(int c8=0;c8<8;c8++){
        int kb=sec*64+c8*8;                 // bf16-pair index (8 pairs = 16 k)
        uint4 xa=*(const uint4*)(xjrow+kb*4);
        uint4 xb=*(const uint4*)(xjrow+kb*4+16);
        uint4 ha=*(const uint4*)(sm+OFF_HIS+kb*4);
        uint4 hb=*(const uint4*)(sm+OFF_HIS+kb*4+16);
        uint32_t hx[8]={ha.x,ha.y,ha.z,ha.w,hb.x,hb.y,hb.z,hb.w};
        uint32_t xx[8]={xa.x,xa.y,xa.z,xa.w,xb.x,xb.y,xb.z,xb.w};
        uint32_t v[4];
#pragma unroll
        for(int q=0;q<4;q++){
          __nv_bfloat162 h0=*(__nv_bfloat162*)&hx[2*q],   x0=*(__nv_bfloat162*)&xx[2*q];
          __nv_bfloat162 h1=*(__nv_bfloat162*)&hx[2*q+1], x1=*(__nv_bfloat162*)&xx[2*q+1];
          __nv_bfloat162 r0=sec?__hmul2(h0,x0):__habs2(__hsub2(h0,x0));
          __nv_bfloat162 r1=sec?__hmul2(h1,x1):__habs2(__hsub2(h1,x1));
          float2 f0=__bfloat1622float2(r0), f1=__bfloat1622float2(r1);
          v[q]=pk16(cvt8(f0.y,f0.x),cvt8(f1.y,f1.x));
        }
        *(uint4*)(sm+OFF_F+f8off((uint32_t)j,(uint32_t)(sec*8+c8)))=*(uint4*)v;
      }
      if(tid<128){  // scalar feats chunk 16: bytes bv,sb,cv,sc + 12 zeros
        float bv=fminf(fmaxf(base[((size_t)(b*NN)+i)*NN+j0+j],-20.f),20.f);
        float cv=fminf(fmaxf(comp[((size_t)(b*NN)+i)*NN+j0+j],-20.f),20.f);
        float sb=1.f/(1.f+__expf(-bv)), sc=1.f/(1.f+__expf(-cv));
        uint32_t v[4]={pk16(cvt8(sb,bv),cvt8(sc,cv)),0u,0u,0u};
        *(uint4*)(sm+OFF_F+f8off((uint32_t)j,16))=*(uint4*)v;
      }
    }
    __syncthreads();

    // ---- GEMM: 9 k-steps of m16n8k32 e4m3 (288 fp8 cols, tail zero-padded) ----
    float c[2][8][4];
#pragma unroll
    for(int mt=0;mt<2;mt++)
#pragma unroll
      for(int nt=0;nt<8;nt++)
#pragma unroll
        for(int e=0;e<4;e++) c[mt][nt][e]=0.f;

    for(int ks=0;ks<9;ks++){
      uint32_t k2=(uint32_t)ks*32u;
      uint32_t a[2][4], bf[8][2];
      LDSM4(a[0][0],a[0][1],a[0][2],a[0][3], smb+((offA+k2)^xr));
      LDSM4(a[1][0],a[1][1],a[1][2],a[1][3], smb+((offA+16*288u+k2)^xr));
#pragma unroll
      for(int q=0;q<4;q++){
        LDSM4(bf[2*q][0],bf[2*q][1],bf[2*q+1][0],bf[2*q+1][1], smb+((offB[q]+k2)^xr));
      }
#pragma unroll
      for(int mt=0;mt<2;mt++)
#pragma unroll
        for(int nt=0;nt<8;nt++)
          MMAFP8(c[mt][nt],a[mt],bf[nt]);
    }

    // epilogue
    {
      int ch=hw>>6;
      float2 ai8[8];
#pragma unroll
      for(int nt=0;nt<8;nt++)
        ai8[nt]=*(float2*)(sm+OFF_AI+(hw+nt*8+2*(lane&3))*4);
      float p[4];
#pragma unroll
      for(int r=0;r<4;r++) p[r]=0.f;
#pragma unroll
      for(int mt=0;mt<2;mt++){
#pragma unroll
        for(int rh=0;rh<2;rh++){
          int j=jw+mt*16+rh*8+(lane>>2);
#pragma unroll
          for(int nt=0;nt<8;nt++){
            int hb=hw+nt*8+2*(lane&3);
            float2 bj=__bfloat1622float2(*(__nv_bfloat162*)(sm+OFF_BJ+(j*66+(hb>>1))*4));
            p[mt*2+rh]+=fmaxf(c[mt][nt][rh*2]  +ai8[nt].x+bj.x,0.f)*w28[nt].x
                       +fmaxf(c[mt][nt][rh*2+1]+ai8[nt].y+bj.y,0.f)*w28[nt].y;
          }
        }
      }
#pragma unroll
      for(int r=0;r<4;r++){
        p[r]+=__shfl_xor_sync(0xffffffffu,p[r],1);
        p[r]+=__shfl_xor_sync(0xffffffffu,p[r],2);
      }
      if((lane&3)==0){
#pragma unroll
        for(int r=0;r<4;r++){
          int j=jw+(r>>1)*16+(r&1)*8+(lane>>2);
          *(float*)(sm+OFF_RED+(j*2+ch)*4)=p[r];
        }
      }
    }
    __syncthreads();
    if(tid<128){
      float v=*(float*)(sm+OFF_RED+tid*8)+*(float*)(sm+OFF_RED+tid*8+4)+b2v;
      out[((size_t)(b*NN)+i)*NN+j0+tid]=v;
    }
    __syncthreads();
  }
}

// ---- Kernel 3: symmetrize + diagonal ----
__global__ void symmetrize(float* __restrict__ out){
  int idx=blockIdx.x*256+threadIdx.x;
  int b=idx>>16, r=idx&65535, i=r>>8, j=r&255;
  float* ob=out+(size_t)b*NN*NN;
  if(j>i){
    float v=0.5f*(ob[i*NN+j]+ob[j*NN+i]);
    ob[i*NN+j]=v; ob[j*NN+i]=v;
  } else if(j==i) ob[i*NN+i]=-1e9f;
}

extern "C" void kernel_launch(void* const* d_in, const int* in_sizes, int n_in,
                              void* d_out, int out_size){
  const float* X   =(const float*)d_in[0];
  const float* base=(const float*)d_in[1];
  const float* comp=(const float*)d_in[2];
  const float* W1  =(const float*)d_in[3];
  const float* b1  =(const float*)d_in[4];
  const float* W2  =(const float*)d_in[5];
  const float* b2  =(const float*)d_in[6];
  float* out=(float*)d_out;

  cudaFuncSetAttribute(precompute_ab,cudaFuncAttributeMaxDynamicSharedMemorySize,PRE_SMEM);
  precompute_ab<<<NB*NN/4,256,PRE_SMEM>>>(X,W1,b1);
  cudaFuncSetAttribute(pair_gemm,cudaFuncAttributeMaxDynamicSharedMemorySize,SMEM_TOT);
  dim3 g(2,16,NB);
  pair_gemm<<<g,256,SMEM_TOT>>>(X,base,comp,W1,W2,b2,out);
  symmetrize<<<NB*NN*NN/256,256>>>(out);
}

// round 12
// speedup vs baseline: 1.2406x; 1.2406x over previous
#include <cuda_runtime.h>
#include <cuda_bf16.h>
#include <cstdint>

#define NB 4
#define NN 256
#define HH 128
typedef unsigned long long ull;

__device__ float g_A[NB*NN*HH];
__device__ float g_Bv[NB*NN*HH];

// smem byte offsets (pair_gemm, bf16 images stride 576B)
#define OFF_F    0          // F image  [128][288] bf16 (swizzled)
#define OFF_W    73728      // Wt image [128][288] bf16 (swizzled)
#define OFF_XJ   147456     // Xj pairs u32 [128 j][68]
#define OFF_BJ   182272     // Bj pairs u32 [128 j][66]
#define OFF_HIS  216064     // hi pairs u32 [64]
#define OFF_AI   216320     // f32[128]
#define OFF_W2   216832     // f32[128]
#define OFF_RED  217344     // f32[128][2]
#define SMEM_TOT 218368

__device__ __forceinline__ uint32_t s32(const void* p){
  uint32_t a; asm("{ .reg .u64 t; cvta.to.shared.u64 t, %1; cvt.u32.u64 %0, t; }":"=r"(a):"l"(p)); return a;
}
__device__ __forceinline__ uint32_t foff(uint32_t r, uint32_t k){
  return ((r*576u + k*2u) ^ ((r&7u)<<4));
}
__device__ __forceinline__ uint32_t f2bf(float a,float b){
  __nv_bfloat162 t=__floats2bfloat162_rn(a,b); return *(uint32_t*)&t;
}
__device__ __forceinline__ void cpa16(void* dst,const void* src){
  unsigned d=(unsigned)__cvta_generic_to_shared(dst);
  asm volatile("cp.async.cg.shared.global [%0],[%1],16;\n"::"r"(d),"l"(src));
}
__device__ __forceinline__ void cpcommit(){ asm volatile("cp.async.commit_group;\n"); }

#define LDSM4(r0,r1,r2,r3,a) asm volatile( \
  "ldmatrix.sync.aligned.m8n8.x4.shared.b16 {%0,%1,%2,%3},[%4];" \
  :"=r"(r0),"=r"(r1),"=r"(r2),"=r"(r3):"r"(a))
#define MMA16816(c,a,b) asm volatile( \
  "mma.sync.aligned.m16n8k16.row.col.f32.bf16.bf16.f32 " \
  "{%0,%1,%2,%3},{%4,%5,%6,%7},{%8,%9},{%0,%1,%2,%3};" \
  :"+f"((c)[0]),"+f"((c)[1]),"+f"((c)[2]),"+f"((c)[3]) \
  :"r"((a)[0]),"r"((a)[1]),"r"((a)[2]),"r"((a)[3]),"r"((b)[0]),"r"((b)[1]))

extern __shared__ __align__(1024) char dynsm[];

// ---- Kernel 1: per-node halves (validated) ----
#define PRE_SMEM (4*HH*4 + 2*2*32*HH*4)
__global__ void __launch_bounds__(256)
precompute_ab(const float* __restrict__ X,
              const float* __restrict__ W1,
              const float* __restrict__ b1){
  float* Xs=(float*)dynsm;
  float* Ws=(float*)(dynsm+4*HH*4);
  int r0=blockIdx.x*4;
  int tid=threadIdx.x;
  int h=tid&127, s=tid>>7;

  for(int e=tid;e<4*HH/4;e+=256)
    ((float4*)Xs)[e]=((const float4*)(X+(size_t)r0*HH))[e];

  #define STAGE(c,buf) do{ \
    for(int e=tid;e<2*32*HH/4;e+=256){ \
      int sh=e>=(32*HH/4); int le=e-sh*(32*HH/4); \
      cpa16((float4*)(Ws+(buf)*2*32*HH+sh*32*HH)+le, \
            (const float4*)(W1+((size_t)(sh*HH+(c)*32))*HH)+le); \
    } cpcommit(); }while(0)

  STAGE(0,0);
  float acc[4]={0.f,0.f,0.f,0.f};
  for(int c=0;c<4;c++){
    if(c<3){ STAGE(c+1,(c+1)&1); asm volatile("cp.async.wait_group 1;\n"); }
    else   { asm volatile("cp.async.wait_group 0;\n"); }
    __syncthreads();
    const float* wp=Ws+(c&1)*2*32*HH+s*32*HH;
#pragma unroll 8
    for(int kk=0;kk<32;kk++){
      float wv=wp[kk*HH+h];
      int k=c*32+kk;
#pragma unroll
      for(int r=0;r<4;r++) acc[r]+=Xs[r*HH+k]*wv;
    }
    __syncthreads();
  }
  if(s==0){
    float bb=b1[h];
#pragma unroll
    for(int r=0;r<4;r++) g_A[(size_t)(r0+r)*HH+h]=acc[r]+bb;
  } else {
#pragma unroll
    for(int r=0;r<4;r++) g_Bv[(size_t)(r0+r)*HH+h]=acc[r];
  }
  #undef STAGE
}

// ---- Kernel 2: bf16 HMMA GEMM, software-pipelined k-loop ----
__global__ void __launch_bounds__(256,1)
pair_gemm(const float* __restrict__ X,const float* __restrict__ base,
          const float* __restrict__ comp,const float* __restrict__ W1,
          const float* __restrict__ W2,const float* __restrict__ b2,
          float* __restrict__ out){
  char* sm=dynsm;
  uint32_t smb=s32(sm);
  int tid=threadIdx.x, w=tid>>5, lane=tid&31;
  int jt=blockIdx.x, ig=blockIdx.y, b=blockIdx.z;
  int j0=jt*128;
  int jw=(w&3)*32, hw=(w>>2)*64;
  float b2v=b2[0];

  // ---- once: W image ----
  {
    int h=tid&127, halfk=tid>>7;
    for(int c8=0;c8<16;c8++){
      int k0=halfk*128+c8*8;
      uint32_t v[4];
#pragma unroll
      for(int q=0;q<4;q++)
        v[q]=f2bf(W1[(256+k0+2*q)*HH+h], W1[(256+k0+2*q+1)*HH+h]);
      *(float4*)(sm+OFF_W+foff(h,k0))=*(float4*)v;
    }
    if(tid<128){
      uint32_t v[4]={f2bf(W1[512*HH+h],W1[513*HH+h]),
                     f2bf(W1[514*HH+h],W1[515*HH+h]),0u,0u};
      *(float4*)(sm+OFF_W+foff(h,256))=*(float4*)v;
      uint32_t z[4]={0u,0u,0u,0u};
      *(float4*)(sm+OFF_W+foff(h,264))=*(float4*)z;
      *(float4*)(sm+OFF_F+foff(h,264))=*(float4*)z;
    }
  }
  // ---- once: Xj pairs [j][kp], Bj pairs [j][hp] ----
  for(int idx=tid;idx<64*128;idx+=256){
    int kp=idx&63, j=idx>>6;
    float2 xv=*(const float2*)(X+(size_t)(b*NN+j0+j)*HH+2*kp);
    *(uint32_t*)(sm+OFF_XJ+(j*68+kp)*4)=f2bf(xv.x,xv.y);
  }
  for(int idx=tid;idx<64*128;idx+=256){
    int hp=idx&63, j=idx>>6;
    float2 bv=*(const float2*)(g_Bv+(size_t)(b*NN+j0+j)*HH+2*hp);
    *(uint32_t*)(sm+OFF_BJ+(j*66+hp)*4)=f2bf(bv.x,bv.y);
  }
  if(tid<32) ((float4*)(sm+OFF_W2))[tid]=((const float4*)W2)[tid];

  // stage first i's HIS/AI
  {
    int i=ig*16;
    if(tid<64){
      float2 xv=*(const float2*)(X+(size_t)(b*NN+i)*HH+2*tid);
      *(uint32_t*)(sm+OFF_HIS+tid*4)=f2bf(xv.x,xv.y);
    } else if(tid>=128&&tid<160){
      ((float4*)(sm+OFF_AI))[tid-128]=((const float4*)(g_A+(size_t)(b*NN+i)*HH))[tid-128];
    }
  }
  __syncthreads();

  uint32_t xr=(uint32_t)((lane&7)<<4);
  uint32_t offA = OFF_F + (uint32_t)(jw+(lane&15))*576u + (uint32_t)((lane>>4)*8)*2u;
  uint32_t offB[4];
#pragma unroll
  for(int q=0;q<4;q++){
    uint32_t rB=(uint32_t)(hw + q*16 + (lane&7) + ((lane>>4)<<3));
    offB[q]= OFF_W + rB*576u + (uint32_t)(((lane>>3)&1)*8)*2u;
  }

  float2 w28[8];
#pragma unroll
  for(int nt=0;nt<8;nt++)
    w28[nt]=*(float2*)(sm+OFF_W2+(hw+nt*8+2*(lane&3))*4);

  for(int itn=0;itn<16;itn++){
    int i=ig*16+itn;

    // build F (vectorized)
    {
      int j=tid&127, sec=tid>>7;
      const char* xjrow=sm+OFF_XJ+(size_t)j*272;
#pragma unroll 4
      for(int c8=0;c8<16;c8++){
        uint4 xv=*(const uint4*)(xjrow+c8*16);
        uint4 hv=*(const uint4*)(sm+OFF_HIS+c8*16);
        uint32_t v[4];
        uint32_t hx[4]={hv.x,hv.y,hv.z,hv.w};
        uint32_t xx[4]={xv.x,xv.y,xv.z,xv.w};
#pragma unroll
        for(int q=0;q<4;q++){
          __nv_bfloat162 h2=*(__nv_bfloat162*)&hx[q];
          __nv_bfloat162 x2=*(__nv_bfloat162*)&xx[q];
          __nv_bfloat162 r=sec?__hmul2(h2,x2):__habs2(__hsub2(h2,x2));
          v[q]=*(uint32_t*)&r;
        }
        *(float4*)(sm+OFF_F+foff((uint32_t)j,(uint32_t)(sec*128+c8*8)))=*(float4*)v;
      }
      if(tid<128){
        float bv=fminf(fmaxf(base[((size_t)(b*NN)+i)*NN+j0+j],-20.f),20.f);
        float cv=fminf(fmaxf(comp[((size_t)(b*NN)+i)*NN+j0+j],-20.f),20.f);
        float sb=1.f/(1.f+__expf(-bv)), sc=1.f/(1.f+__expf(-cv));
        uint32_t v[4]={f2bf(bv,sb),f2bf(cv,sc),0u,0u};
        *(float4*)(sm+OFF_F+foff((uint32_t)j,256))=*(float4*)v;
      }
    }
    __syncthreads();

    // ---- GEMM: 17 k-steps, fully unrolled, double-buffered fragments ----
    float c[2][8][4];
#pragma unroll
    for(int mt=0;mt<2;mt++)
#pragma unroll
      for(int nt=0;nt<8;nt++)
#pragma unroll
        for(int e=0;e<4;e++) c[mt][nt][e]=0.f;

    uint32_t a[2][2][4], bfr[2][8][2];

    #define LOADF(ks,buf) do{ uint32_t k2=(uint32_t)(ks)*32u; \
      LDSM4(a[buf][0][0],a[buf][0][1],a[buf][0][2],a[buf][0][3], smb+((offA+k2)^xr)); \
      LDSM4(a[buf][1][0],a[buf][1][1],a[buf][1][2],a[buf][1][3], smb+((offA+16*576u+k2)^xr)); \
      LDSM4(bfr[buf][0][0],bfr[buf][0][1],bfr[buf][1][0],bfr[buf][1][1], smb+((offB[0]+k2)^xr)); \
      LDSM4(bfr[buf][2][0],bfr[buf][2][1],bfr[buf][3][0],bfr[buf][3][1], smb+((offB[1]+k2)^xr)); \
      LDSM4(bfr[buf][4][0],bfr[buf][4][1],bfr[buf][5][0],bfr[buf][5][1], smb+((offB[2]+k2)^xr)); \
      LDSM4(bfr[buf][6][0],bfr[buf][6][1],bfr[buf][7][0],bfr[buf][7][1], smb+((offB[3]+k2)^xr)); \
    }while(0)

    LOADF(0,0);
#pragma unroll
    for(int ks=0;ks<17;ks++){
      int cur=ks&1, nxt=cur^1;
      if(ks<16) LOADF(ks+1,nxt);
#pragma unroll
      for(int mt=0;mt<2;mt++)
#pragma unroll
        for(int nt=0;nt<8;nt++)
          MMA16816(c[mt][nt],a[cur][mt],bfr[cur][nt]);
    }
    #undef LOADF

    // epilogue
    {
      int ch=hw>>6;
      float2 ai8[8];
#pragma unroll
      for(int nt=0;nt<8;nt++)
        ai8[nt]=*(float2*)(sm+OFF_AI+(hw+nt*8+2*(lane&3))*4);
      float p[4];
#pragma unroll
      for(int r=0;r<4;r++) p[r]=0.f;
#pragma unroll
      for(int mt=0;mt<2;mt++){
#pragma unroll
        for(int rh=0;rh<2;rh++){
          int j=jw+mt*16+rh*8+(lane>>2);
#pragma unroll
          for(int nt=0;nt<8;nt++){
            int hb=hw+nt*8+2*(lane&3);
            float2 bj=__bfloat1622float2(*(__nv_bfloat162*)(sm+OFF_BJ+(j*66+(hb>>1))*4));
            p[mt*2+rh]+=fmaxf(c[mt][nt][rh*2]  +ai8[nt].x+bj.x,0.f)*w28[nt].x
                       +fmaxf(c[mt][nt][rh*2+1]+ai8[nt].y+bj.y,0.f)*w28[nt].y;
          }
        }
      }
#pragma unroll
      for(int r=0;r<4;r++){
        p[r]+=__shfl_xor_sync(0xffffffffu,p[r],1);
        p[r]+=__shfl_xor_sync(0xffffffffu,p[r],2);
      }
      if((lane&3)==0){
#pragma unroll
        for(int r=0;r<4;r++){
          int j=jw+(r>>1)*16+(r&1)*8+(lane>>2);
          *(float*)(sm+OFF_RED+(j*2+ch)*4)=p[r];
        }
      }
    }
    __syncthreads();

    // writeback + stage next i's HIS/AI (disjoint smem regions)
    if(tid<128){
      float v=*(float*)(sm+OFF_RED+tid*8)+*(float*)(sm+OFF_RED+tid*8+4)+b2v;
      out[((size_t)(b*NN)+i)*NN+j0+tid]=v;
    }
    if(itn<15){
      int i2=i+1;
      if(tid<64){
        float2 xv=*(const float2*)(X+(size_t)(b*NN+i2)*HH+2*tid);
        *(uint32_t*)(sm+OFF_HIS+tid*4)=f2bf(xv.x,xv.y);
      } else if(tid>=128&&tid<160){
        ((float4*)(sm+OFF_AI))[tid-128]=((const float4*)(g_A+(size_t)(b*NN+i2)*HH))[tid-128];
      }
    }
    __syncthreads();
  }
}

// ---- Kernel 3: symmetrize + diagonal ----
__global__ void symmetrize(float* __restrict__ out){
  int idx=blockIdx.x*256+threadIdx.x;
  int b=idx>>16, r=idx&65535, i=r>>8, j=r&255;
  float* ob=out+(size_t)b*NN*NN;
  if(j>i){
    float v=0.5f*(ob[i*NN+j]+ob[j*NN+i]);
    ob[i*NN+j]=v; ob[j*NN+i]=v;
  } else if(j==i) ob[i*NN+i]=-1e9f;
}

extern "C" void kernel_launch(void* const* d_in, const int* in_sizes, int n_in,
                              void* d_out, int out_size){
  const float* X   =(const float*)d_in[0];
  const float* base=(const float*)d_in[1];
  const float* comp=(const float*)d_in[2];
  const float* W1  =(const float*)d_in[3];
  const float* b1  =(const float*)d_in[4];
  const float* W2  =(const float*)d_in[5];
  const float* b2  =(const float*)d_in[6];
  float* out=(float*)d_out;

  cudaFuncSetAttribute(precompute_ab,cudaFuncAttributeMaxDynamicSharedMemorySize,PRE_SMEM);
  precompute_ab<<<NB*NN/4,256,PRE_SMEM>>>(X,W1,b1);
  cudaFuncSetAttribute(pair_gemm,cudaFuncAttributeMaxDynamicSharedMemorySize,SMEM_TOT);
  dim3 g(2,16,NB);
  pair_gemm<<<g,256,SMEM_TOT>>>(X,base,comp,W1,W2,b2,out);
  symmetrize<<<NB*NN*NN/256,256>>>(out);
}

// round 14
// speedup vs baseline: 1.4111x; 1.1374x over previous
#include <cuda_runtime.h>
#include <cuda_bf16.h>
#include <cstdint>

#define NB 4
#define NN 256
#define HH 128
typedef unsigned long long ull;

__device__ float g_A[NB*NN*HH];
__device__ float g_Bv[NB*NN*HH];

// smem byte offsets (pair_gemm)
#define OFF_W    0          // Wt image [128 h][288 k] bf16 swizzled, stride 576B
#define OFF_XJ   73728      // Xj bf16 pairs u32 [64 kp][136 stride] (34816B)
#define OFF_BJ   108544     // Bj bf16 pairs u32 [128 j][66]         (33792B)
#define OFF_HIS  142336     // hi bf16 pairs u32 [64]
#define OFF_AI   142592     // f32[128]
#define OFF_W2   143104     // f32[128]
#define OFF_SCF  143616     // u32 [128 j][2]  (bv,sb),(cv,sc) bf16 pairs
#define OFF_RED  144640     // f32[128][2]
#define SMEM_TOT 145664

__device__ __forceinline__ uint32_t s32(const void* p){
  uint32_t a; asm("{ .reg .u64 t; cvta.to.shared.u64 t, %1; cvt.u32.u64 %0, t; }":"=r"(a):"l"(p)); return a;
}
__device__ __forceinline__ uint32_t foff(uint32_t r, uint32_t k){
  return ((r*576u + k*2u) ^ ((r&7u)<<4));
}
__device__ __forceinline__ uint32_t f2bf(float a,float b){
  __nv_bfloat162 t=__floats2bfloat162_rn(a,b); return *(uint32_t*)&t;
}
__device__ __forceinline__ uint32_t habsub2(uint32_t h,uint32_t x){
  __nv_bfloat162 r=__habs2(__hsub2(*(__nv_bfloat162*)&h,*(__nv_bfloat162*)&x));
  return *(uint32_t*)&r;
}
__device__ __forceinline__ uint32_t hmul2u(uint32_t h,uint32_t x){
  __nv_bfloat162 r=__hmul2(*(__nv_bfloat162*)&h,*(__nv_bfloat162*)&x);
  return *(uint32_t*)&r;
}
__device__ __forceinline__ void cpa16(void* dst,const void* src){
  unsigned d=(unsigned)__cvta_generic_to_shared(dst);
  asm volatile("cp.async.cg.shared.global [%0],[%1],16;\n"::"r"(d),"l"(src));
}
__device__ __forceinline__ void cpcommit(){ asm volatile("cp.async.commit_group;\n"); }

#define LDSM4(r0,r1,r2,r3,a) asm volatile( \
  "ldmatrix.sync.aligned.m8n8.x4.shared.b16 {%0,%1,%2,%3},[%4];" \
  :"=r"(r0),"=r"(r1),"=r"(r2),"=r"(r3):"r"(a))
#define MMA16816(c,a,b) asm volatile( \
  "mma.sync.aligned.m16n8k16.row.col.f32.bf16.bf16.f32 " \
  "{%0,%1,%2,%3},{%4,%5,%6,%7},{%8,%9},{%0,%1,%2,%3};" \
  :"+f"((c)[0]),"+f"((c)[1]),"+f"((c)[2]),"+f"((c)[3]) \
  :"r"((a)[0]),"r"((a)[1]),"r"((a)[2]),"r"((a)[3]),"r"((b)[0]),"r"((b)[1]))

extern __shared__ __align__(1024) char dynsm[];

// ---- Kernel 1: per-node halves (validated) ----
#define PRE_SMEM (4*HH*4 + 2*2*32*HH*4)
__global__ void __launch_bounds__(256)
precompute_ab(const float* __restrict__ X,
              const float* __restrict__ W1,
              const float* __restrict__ b1){
  float* Xs=(float*)dynsm;
  float* Ws=(float*)(dynsm+4*HH*4);
  int r0=blockIdx.x*4;
  int tid=threadIdx.x;
  int h=tid&127, s=tid>>7;

  for(int e=tid;e<4*HH/4;e+=256)
    ((float4*)Xs)[e]=((const float4*)(X+(size_t)r0*HH))[e];

  #define STAGE(c,buf) do{ \
    for(int e=tid;e<2*32*HH/4;e+=256){ \
      int sh=e>=(32*HH/4); int le=e-sh*(32*HH/4); \
      cpa16((float4*)(Ws+(buf)*2*32*HH+sh*32*HH)+le, \
            (const float4*)(W1+((size_t)(sh*HH+(c)*32))*HH)+le); \
    } cpcommit(); }while(0)

  STAGE(0,0);
  float acc[4]={0.f,0.f,0.f,0.f};
  for(int c=0;c<4;c++){
    if(c<3){ STAGE(c+1,(c+1)&1); asm volatile("cp.async.wait_group 1;\n"); }
    else   { asm volatile("cp.async.wait_group 0;\n"); }
    __syncthreads();
    const float* wp=Ws+(c&1)*2*32*HH+s*32*HH;
#pragma unroll 8
    for(int kk=0;kk<32;kk++){
      float wv=wp[kk*HH+h];
      int k=c*32+kk;
#pragma unroll
      for(int r=0;r<4;r++) acc[r]+=Xs[r*HH+k]*wv;
    }
    __syncthreads();
  }
  if(s==0){
    float bb=b1[h];
#pragma unroll
    for(int r=0;r<4;r++) g_A[(size_t)(r0+r)*HH+h]=acc[r]+bb;
  } else {
#pragma unroll
    for(int r=0;r<4;r++) g_Bv[(size_t)(r0+r)*HH+h]=acc[r];
  }
  #undef STAGE
}

// ---- Kernel 2: bf16 HMMA GEMM, A-fragments computed in registers ----
__global__ void __launch_bounds__(256,1)
pair_gemm(const float* __restrict__ X,const float* __restrict__ base,
          const float* __restrict__ comp,const float* __restrict__ W1,
          const float* __restrict__ W2,const float* __restrict__ b2,
          float* __restrict__ out){
  char* sm=dynsm;
  uint32_t smb=s32(sm);
  int tid=threadIdx.x, w=tid>>5, lane=tid&31;
  int jt=blockIdx.x, ig=blockIdx.y, b=blockIdx.z;
  int j0=jt*128;
  int jw=(w&3)*32, hw=(w>>2)*64;
  int qr=lane>>2, tql=lane&3;
  float b2v=b2[0];

  // ---- once: W image (bf16, swizzled) ----
  {
    int h=tid&127, halfk=tid>>7;
    for(int c8=0;c8<16;c8++){
      int k0=halfk*128+c8*8;
      uint32_t v[4];
#pragma unroll
      for(int q=0;q<4;q++)
        v[q]=f2bf(W1[(256+k0+2*q)*HH+h], W1[(256+k0+2*q+1)*HH+h]);
      *(float4*)(sm+OFF_W+foff(h,k0))=*(float4*)v;
    }
    if(tid<128){
      uint32_t v[4]={f2bf(W1[512*HH+h],W1[513*HH+h]),
                     f2bf(W1[514*HH+h],W1[515*HH+h]),0u,0u};
      *(float4*)(sm+OFF_W+foff(h,256))=*(float4*)v;
      uint32_t z[4]={0u,0u,0u,0u};
      *(float4*)(sm+OFF_W+foff(h,264))=*(float4*)z;
    }
  }
  // ---- once: Xj pairs [kp][j] stride 136, Bj pairs [j][hp] stride 66 ----
  for(int idx=tid;idx<64*128;idx+=256){
    int kp=idx&63, j=idx>>6;
    float2 xv=*(const float2*)(X+(size_t)(b*NN+j0+j)*HH+2*kp);
    *(uint32_t*)(sm+OFF_XJ+(kp*136+j)*4)=f2bf(xv.x,xv.y);
  }
  for(int idx=tid;idx<64*128;idx+=256){
    int hp=idx&63, j=idx>>6;
    float2 bv=*(const float2*)(g_Bv+(size_t)(b*NN+j0+j)*HH+2*hp);
    *(uint32_t*)(sm+OFF_BJ+(j*66+hp)*4)=f2bf(bv.x,bv.y);
  }
  if(tid<32) ((float4*)(sm+OFF_W2))[tid]=((const float4*)W2)[tid];

  // ---- stage first i: HIS, AI, SCF ----
  {
    int i=ig*16;
    if(tid<64){
      float2 xv=*(const float2*)(X+(size_t)(b*NN+i)*HH+2*tid);
      *(uint32_t*)(sm+OFF_HIS+tid*4)=f2bf(xv.x,xv.y);
    } else if(tid<96){
      ((float4*)(sm+OFF_AI))[tid-64]=((const float4*)(g_A+(size_t)(b*NN+i)*HH))[tid-64];
    } else if(tid>=128){
      int j=tid-128;
      float bv=fminf(fmaxf(base[((size_t)(b*NN)+i)*NN+j0+j],-20.f),20.f);
      float cv=fminf(fmaxf(comp[((size_t)(b*NN)+i)*NN+j0+j],-20.f),20.f);
      float sb=1.f/(1.f+__expf(-bv)), sc=1.f/(1.f+__expf(-cv));
      *(uint32_t*)(sm+OFF_SCF+(j*2+0)*4)=f2bf(bv,sb);
      *(uint32_t*)(sm+OFF_SCF+(j*2+1)*4)=f2bf(cv,sc);
    }
  }
  __syncthreads();

  uint32_t xr=(uint32_t)((lane&7)<<4);
  uint32_t offB[4];
#pragma unroll
  for(int q=0;q<4;q++){
    uint32_t rB=(uint32_t)(hw + q*16 + (lane&7) + ((lane>>4)<<3));
    offB[q]= OFF_W + rB*576u + (uint32_t)(((lane>>3)&1)*8)*2u;
  }

  float2 w28[8];
#pragma unroll
  for(int nt=0;nt<8;nt++)
    w28[nt]=*(float2*)(sm+OFF_W2+(hw+nt*8+2*(lane&3))*4);

  for(int itn=0;itn<16;itn++){
    int i=ig*16+itn;

    float c[2][8][4];
#pragma unroll
    for(int mt=0;mt<2;mt++)
#pragma unroll
      for(int nt=0;nt<8;nt++)
#pragma unroll
        for(int e=0;e<4;e++) c[mt][nt][e]=0.f;

    uint32_t a[2][2][4], bfr[2][8][2];

    // A-fragment for main k-step ks (0..15): pairs wrap at 64 (k' 128..255 reuse hi/xj)
    #define MAKEA(ks,buf) do{ \
      int kp0=8*((ks)&7)+tql; \
      uint32_t h0=*(uint32_t*)(sm+OFF_HIS+kp0*4); \
      uint32_t h1=*(uint32_t*)(sm+OFF_HIS+(kp0+4)*4); \
      _Pragma("unroll") \
      for(int mt=0;mt<2;mt++){ \
        int r=jw+qr+mt*16; \
        uint32_t x0=*(uint32_t*)(sm+OFF_XJ+(kp0*136+r)*4); \
        uint32_t x1=*(uint32_t*)(sm+OFF_XJ+(kp0*136+r+8)*4); \
        uint32_t x2=*(uint32_t*)(sm+OFF_XJ+((kp0+4)*136+r)*4); \
        uint32_t x3=*(uint32_t*)(sm+OFF_XJ+((kp0+4)*136+r+8)*4); \
        if((ks)<8){ \
          a[buf][mt][0]=habsub2(h0,x0); a[buf][mt][1]=habsub2(h0,x1); \
          a[buf][mt][2]=habsub2(h1,x2); a[buf][mt][3]=habsub2(h1,x3); \
        } else { \
          a[buf][mt][0]=hmul2u(h0,x0); a[buf][mt][1]=hmul2u(h0,x1); \
          a[buf][mt][2]=hmul2u(h1,x2); a[buf][mt][3]=hmul2u(h1,x3); \
        } \
      } \
    }while(0)

    // A-fragment for k-step 16 (scalar features from SCF; cols >=260 zero)
    #define MAKEA16(buf) do{ \
      _Pragma("unroll") \
      for(int mt=0;mt<2;mt++){ \
        int r=jw+qr+mt*16; \
        a[buf][mt][0]=(tql<2)?*(uint32_t*)(sm+OFF_SCF+(r*2+tql)*4):0u; \
        a[buf][mt][1]=(tql<2)?*(uint32_t*)(sm+OFF_SCF+((r+8)*2+tql)*4):0u; \
        a[buf][mt][2]=0u; a[buf][mt][3]=0u; \
      } \
    }while(0)

    #define LOADB(ks,buf) do{ uint32_t k2=(uint32_t)(ks)*32u; \
      LDSM4(bfr[buf][0][0],bfr[buf][0][1],bfr[buf][1][0],bfr[buf][1][1], smb+((offB[0]+k2)^xr)); \
      LDSM4(bfr[buf][2][0],bfr[buf][2][1],bfr[buf][3][0],bfr[buf][3][1], smb+((offB[1]+k2)^xr)); \
      LDSM4(bfr[buf][4][0],bfr[buf][4][1],bfr[buf][5][0],bfr[buf][5][1], smb+((offB[2]+k2)^xr)); \
      LDSM4(bfr[buf][6][0],bfr[buf][6][1],bfr[buf][7][0],bfr[buf][7][1], smb+((offB[3]+k2)^xr)); \
    }while(0)

    MAKEA(0,0);
    LOADB(0,0);
#pragma unroll
    for(int ks=0;ks<17;ks++){
      int cur=ks&1, nxt=cur^1;
      if(ks<15)       MAKEA(ks+1,nxt);
      else if(ks==15) MAKEA16(nxt);
      if(ks<16)       LOADB(ks+1,nxt);
#pragma unroll
      for(int mt=0;mt<2;mt++)
#pragma unroll
        for(int nt=0;nt<8;nt++)
          MMA16816(c[mt][nt],a[cur][mt],bfr[cur][nt]);
    }
    #undef MAKEA
    #undef MAKEA16
    #undef LOADB

    // epilogue
    {
      int ch=hw>>6;
      float2 ai8[8];
#pragma unroll
      for(int nt=0;nt<8;nt++)
        ai8[nt]=*(float2*)(sm+OFF_AI+(hw+nt*8+2*(lane&3))*4);
      float p[4];
#pragma unroll
      for(int r=0;r<4;r++) p[r]=0.f;
#pragma unroll
      for(int mt=0;mt<2;mt++){
#pragma unroll
        for(int rh=0;rh<2;rh++){
          int j=jw+mt*16+rh*8+(lane>>2);
#pragma unroll
          for(int nt=0;nt<8;nt++){
            int hb=hw+nt*8+2*(lane&3);
            float2 bj=__bfloat1622float2(*(__nv_bfloat162*)(sm+OFF_BJ+(j*66+(hb>>1))*4));
            p[mt*2+rh]+=fmaxf(c[mt][nt][rh*2]  +ai8[nt].x+bj.x,0.f)*w28[nt].x
                       +fmaxf(c[mt][nt][rh*2+1]+ai8[nt].y+bj.y,0.f)*w28[nt].y;
          }
        }
      }
#pragma unroll
      for(int r=0;r<4;r++){
        p[r]+=__shfl_xor_sync(0xffffffffu,p[r],1);
        p[r]+=__shfl_xor_sync(0xffffffffu,p[r],2);
      }
      if((lane&3)==0){
#pragma unroll
        for(int r=0;r<4;r++){
          int j=jw+(r>>1)*16+(r&1)*8+(lane>>2);
          *(float*)(sm+OFF_RED+(j*2+ch)*4)=p[r];
        }
      }
    }
    __syncthreads();

    // writeback(i) + stage(i+1)
    if(tid<128){
      float v=*(float*)(sm+OFF_RED+tid*8)+*(float*)(sm+OFF_RED+tid*8+4)+b2v;
      out[((size_t)(b*NN)+i)*NN+j0+tid]=v;
    }
    if(itn<15){
      int i2=i+1;
      if(tid<64){
        float2 xv=*(const float2*)(X+(size_t)(b*NN+i2)*HH+2*tid);
        *(uint32_t*)(sm+OFF_HIS+tid*4)=f2bf(xv.x,xv.y);
      } else if(tid<96){
        ((float4*)(sm+OFF_AI))[tid-64]=((const float4*)(g_A+(size_t)(b*NN+i2)*HH))[tid-64];
      } else if(tid>=128){
        int j=tid-128;
        float bv=fminf(fmaxf(base[((size_t)(b*NN)+i2)*NN+j0+j],-20.f),20.f);
        float cv=fminf(fmaxf(comp[((size_t)(b*NN)+i2)*NN+j0+j],-20.f),20.f);
        float sb=1.f/(1.f+__expf(-bv)), sc=1.f/(1.f+__expf(-cv));
        *(uint32_t*)(sm+OFF_SCF+(j*2+0)*4)=f2bf(bv,sb);
        *(uint32_t*)(sm+OFF_SCF+(j*2+1)*4)=f2bf(cv,sc);
      }
    }
    __syncthreads();
  }
}

// ---- Kernel 3: symmetrize + diagonal ----
__global__ void symmetrize(float* __restrict__ out){
  int idx=blockIdx.x*256+threadIdx.x;
  int b=idx>>16, r=idx&65535, i=r>>8, j=r&255;
  float* ob=out+(size_t)b*NN*NN;
  if(j>i){
    float v=0.5f*(ob[i*NN+j]+ob[j*NN+i]);
    ob[i*NN+j]=v; ob[j*NN+i]=v;
  } else if(j==i) ob[i*NN+i]=-1e9f;
}

extern "C" void kernel_launch(void* const* d_in, const int* in_sizes, int n_in,
                              void* d_out, int out_size){
  const float* X   =(const float*)d_in[0];
  const float* base=(const float*)d_in[1];
  const float* comp=(const float*)d_in[2];
  const float* W1  =(const float*)d_in[3];
  const float* b1  =(const float*)d_in[4];
  const float* W2  =(const float*)d_in[5];
  const float* b2  =(const float*)d_in[6];
  float* out=(float*)d_out;

  cudaFuncSetAttribute(precompute_ab,cudaFuncAttributeMaxDynamicSharedMemorySize,PRE_SMEM);
  precompute_ab<<<NB*NN/4,256,PRE_SMEM>>>(X,W1,b1);
  cudaFuncSetAttribute(pair_gemm,cudaFuncAttributeMaxDynamicSharedMemorySize,SMEM_TOT);
  dim3 g(2,16,NB);
  pair_gemm<<<g,256,SMEM_TOT>>>(X,base,comp,W1,W2,b2,out);
  symmetrize<<<NB*NN*NN/256,256>>>(out);
}